// round 15
// baseline (speedup 1.0000x reference)
#include <cuda_runtime.h>

#define HW (1024*1024)
#define NIMG 20

// ---------------- static device scratch ----------------
__device__ float g_S1  [NIMG*HW];        // vertical strip-local prefix of hbox sums
__device__ float g_vp  [NIMG*32*1024];   // per-strip vertical offsets [img][strip][col]
__device__ float g_GL1 [NIMG*512*512];
__device__ float g_GL2 [NIMG*256*256];
__device__ float g_GL3 [NIMG*128*128];
__device__ float g_GL4 [NIMG*64*64];
__device__ float g_GW1 [NIMG*512*512];
__device__ float g_GW2 [NIMG*256*256];
__device__ float g_GW3 [NIMG*128*128];
__device__ float g_GW4 [NIMG*64*64];
__device__ float g_P1  [4*512*512];
__device__ float g_P2  [4*256*256];
__device__ float g_P3  [4*128*128];
__device__ float g_Lpart [NIMG*32];
__device__ float g_wpart [NIMG*1024];
__device__ float g_scale[NIMG];
__device__ int   g_cnt_hv[NIMG];         // per-image strip-completion counters
__device__ int   g_cnt_q;                // quality-block completion counter

// ---- K1: fused horizontal box + vertical strip prefix + folded column offset ----
__global__ void __launch_bounds__(256) k_hvscan(const float* __restrict__ L) {
    int strip = blockIdx.x;            // 0..31
    int img   = blockIdx.y;            // 0..19
    int t = threadIdx.x;
    int lane = t & 31, wid = t >> 5;
    __shared__ float P[2][1024];
    __shared__ float woff[2][8];
    __shared__ float lred[8];
    __shared__ int slast;
    float v0 = 0.f, v1 = 0.f, v2 = 0.f, v3 = 0.f;   // vertical running sums (4 cols)
    float lacc = 0.f;
    size_t base = ((size_t)img * 1024 + strip * 32) * 1024;
    const float4* src = reinterpret_cast<const float4*>(L + base);
    float4* dst = reinterpret_cast<float4*>(g_S1 + base);

    for (int r = 0; r < 32; r += 2) {
        float4 vA = src[r * 256 + t];
        float4 vB = src[(r + 1) * 256 + t];
        lacc += (vA.x + vA.y) + (vA.z + vA.w);
        lacc += (vB.x + vB.y) + (vB.z + vB.w);
        float a0 = fmaxf(vA.x - 0.88f, 0.f), a1 = fmaxf(vA.y - 0.88f, 0.f);
        float a2 = fmaxf(vA.z - 0.88f, 0.f), a3 = fmaxf(vA.w - 0.88f, 0.f);
        float b0 = fmaxf(vB.x - 0.88f, 0.f), b1 = fmaxf(vB.y - 0.88f, 0.f);
        float b2 = fmaxf(vB.z - 0.88f, 0.f), b3 = fmaxf(vB.w - 0.88f, 0.f);
        float pA0 = a0, pA1 = pA0 + a1, pA2 = pA1 + a2, pA3 = pA2 + a3;
        float pB0 = b0, pB1 = pB0 + b1, pB2 = pB1 + b2, pB3 = pB2 + b3;
        float scA = pA3, scB = pB3;
        #pragma unroll
        for (int o = 1; o < 32; o <<= 1) {
            float nA = __shfl_up_sync(0xffffffffu, scA, o);
            float nB = __shfl_up_sync(0xffffffffu, scB, o);
            if (lane >= o) { scA += nA; scB += nB; }
        }
        if (lane == 31) { woff[0][wid] = scA; woff[1][wid] = scB; }
        __syncthreads();
        float bsA = scA - pA3, bsB = scB - pB3;
        #pragma unroll
        for (int i = 0; i < 8; i++) {
            if (i < wid) { bsA += woff[0][i]; bsB += woff[1][i]; }
        }
        P[0][4*t+0] = bsA + pA0;
        P[0][4*t+1] = bsA + pA1;
        P[0][4*t+2] = bsA + pA2;
        P[0][4*t+3] = bsA + pA3;
        P[1][4*t+0] = bsB + pB0;
        P[1][4*t+1] = bsB + pB1;
        P[1][4*t+2] = bsB + pB2;
        P[1][4*t+3] = bsB + pB3;
        __syncthreads();
        int xi = 4*t;
        int hi0 = min(xi + 30, 1023), lo0 = xi - 31;
        int hi1 = min(xi + 31, 1023), lo1 = xi - 30;
        int hi2 = min(xi + 32, 1023), lo2 = xi - 29;
        int hi3 = min(xi + 33, 1023), lo3 = xi - 28;
        {
            float h0 = P[0][hi0] - (lo0 >= 0 ? P[0][lo0] : 0.f);
            float h1 = P[0][hi1] - (lo1 >= 0 ? P[0][lo1] : 0.f);
            float h2 = P[0][hi2] - (lo2 >= 0 ? P[0][lo2] : 0.f);
            float h3 = P[0][hi3] - (lo3 >= 0 ? P[0][lo3] : 0.f);
            v0 += h0; v1 += h1; v2 += h2; v3 += h3;
            float4 o4; o4.x = v0; o4.y = v1; o4.z = v2; o4.w = v3;
            dst[r * 256 + t] = o4;
        }
        {
            float h0 = P[1][hi0] - (lo0 >= 0 ? P[1][lo0] : 0.f);
            float h1 = P[1][hi1] - (lo1 >= 0 ? P[1][lo1] : 0.f);
            float h2 = P[1][hi2] - (lo2 >= 0 ? P[1][lo2] : 0.f);
            float h3 = P[1][hi3] - (lo3 >= 0 ? P[1][lo3] : 0.f);
            v0 += h0; v1 += h1; v2 += h2; v3 += h3;
            float4 o4; o4.x = v0; o4.y = v1; o4.z = v2; o4.w = v3;
            dst[(r + 1) * 256 + t] = o4;
        }
    }
    float4* vpd = reinterpret_cast<float4*>(g_vp + ((size_t)img*32 + strip)*1024);
    float4 tot; tot.x = v0; tot.y = v1; tot.z = v2; tot.w = v3;
    vpd[t] = tot;
    #pragma unroll
    for (int o = 16; o; o >>= 1) lacc += __shfl_down_sync(0xffffffffu, lacc, o);
    if (lane == 0) lred[wid] = lacc;
    __syncthreads();
    if (t == 0) {
        float s = 0.f;
        #pragma unroll
        for (int i = 0; i < 8; i++) s += lred[i];
        g_Lpart[img*32 + strip] = s;
        __threadfence();
        slast = (atomicAdd(&g_cnt_hv[img], 1) == 31) ? 1 : 0;
    }
    __syncthreads();
    // last strip of this image: exclusive prefix over the 32 strip totals per column
    if (slast) {
        float4* p = reinterpret_cast<float4*>(g_vp + (size_t)img*32*1024) + t;
        float4 run = make_float4(0.f, 0.f, 0.f, 0.f);
        #pragma unroll
        for (int c = 0; c < 4; c++) {
            float4 v[8];
            #pragma unroll
            for (int i = 0; i < 8; i++) v[i] = p[(c*8+i)*256];
            #pragma unroll
            for (int i = 0; i < 8; i++) {
                float4 tv = v[i];
                p[(c*8+i)*256] = run;
                run.x += tv.x; run.y += tv.y; run.z += tv.z; run.w += tv.w;
            }
        }
        if (t == 0) g_cnt_hv[img] = 0;   // reset for graph replay
    }
}

// ---------------- K2c: quality + w + folded means/scales -------------------------
__device__ __forceinline__ float quality1(float Lv, float V) {
    const float cb = -15.f / 3721.f;
    float u = 2.f*Lv - 1.f;
    float t1 = 1.f - u*u;
    float baseq = t1*t1;
    float sat  = __fdividef(1.f, 1.f + __expf( 15.f*(Lv - 0.88f)));
    float dark = __fdividef(1.f, 1.f + __expf(-25.f*(Lv - 0.04f)));
    float bloom = __expf(cb * V);
    return fmaxf(baseq*sat*dark*bloom, 0.02f);
}

__global__ void __launch_bounds__(256) k_quality(const float* __restrict__ L,
                                                 float* __restrict__ wout) {
    int t = threadIdx.x;          // float4 index: 256 * 4 = 1024 px per row
    int y = blockIdx.x;
    int b = blockIdx.y;
    int lane = t & 31, wid = t >> 5;
    int ya = min(y + 30, 1023);
    int yb = y - 31;
    float4 q[5];
    float4 qs = make_float4(1e-6f, 1e-6f, 1e-6f, 1e-6f);
    #pragma unroll
    for (int n = 0; n < 5; n++) {
        int img = b*5 + n;
        const float* Sbase  = g_S1 + (size_t)img*HW;
        const float* vpbase = g_vp + (size_t)img*32*1024;
        float4 Sa = reinterpret_cast<const float4*>(Sbase + (size_t)ya*1024)[t];
        float4 va = reinterpret_cast<const float4*>(vpbase + (ya>>5)*1024)[t];
        float4 V;
        V.x = Sa.x + va.x; V.y = Sa.y + va.y; V.z = Sa.z + va.z; V.w = Sa.w + va.w;
        if (yb >= 0) {
            float4 Sb = reinterpret_cast<const float4*>(Sbase + (size_t)yb*1024)[t];
            float4 vb = reinterpret_cast<const float4*>(vpbase + (yb>>5)*1024)[t];
            V.x -= Sb.x + vb.x; V.y -= Sb.y + vb.y; V.z -= Sb.z + vb.z; V.w -= Sb.w + vb.w;
        }
        float4 Lv = reinterpret_cast<const float4*>(L + (size_t)img*HW + (size_t)y*1024)[t];
        float4 qn;
        qn.x = quality1(Lv.x, V.x);
        qn.y = quality1(Lv.y, V.y);
        qn.z = quality1(Lv.z, V.z);
        qn.w = quality1(Lv.w, V.w);
        q[n] = qn;
        qs.x += qn.x; qs.y += qn.y; qs.z += qn.z; qs.w += qn.w;
    }
    float4 inv;
    inv.x = __fdividef(1.f, qs.x); inv.y = __fdividef(1.f, qs.y);
    inv.z = __fdividef(1.f, qs.z); inv.w = __fdividef(1.f, qs.w);
    __shared__ float sred[5][8];
    __shared__ int qlast;
    #pragma unroll
    for (int n = 0; n < 5; n++) {
        float4 wv;
        wv.x = q[n].x*inv.x; wv.y = q[n].y*inv.y;
        wv.z = q[n].z*inv.z; wv.w = q[n].w*inv.w;
        reinterpret_cast<float4*>(wout + (size_t)(b*5+n)*HW + (size_t)y*1024)[t] = wv;
        float s = (wv.x + wv.y) + (wv.z + wv.w);
        #pragma unroll
        for (int o = 16; o; o >>= 1) s += __shfl_down_sync(0xffffffffu, s, o);
        if (lane == 0) sred[n][wid] = s;
    }
    __syncthreads();
    if (t < 5) {
        float s = 0.f;
        #pragma unroll
        for (int i = 0; i < 8; i++) s += sred[t][i];
        g_wpart[(size_t)(b*5+t)*1024 + y] = s;
    }
    if (t == 0) {
        __threadfence();
        qlast = (atomicAdd(&g_cnt_q, 1) == 4095) ? 1 : 0;
    }
    __syncthreads();
    if (!qlast) return;
    // last block: per-image means + exposure scales (deterministic sum order)
    __shared__ float part[2][8];
    __shared__ float Lm[NIMG], wm[NIMG];
    for (int bn = 0; bn < NIMG; bn++) {
        float a = 0.f;
        for (int i = t; i < 1024; i += 256) a += g_wpart[bn*1024 + i];
        float l = (t < 32) ? g_Lpart[bn*32 + t] : 0.f;
        #pragma unroll
        for (int o = 16; o; o >>= 1) {
            a += __shfl_down_sync(0xffffffffu, a, o);
            l += __shfl_down_sync(0xffffffffu, l, o);
        }
        if (lane == 0) { part[0][wid] = a; part[1][wid] = l; }
        __syncthreads();
        if (t == 0) {
            float sw = 0.f, sl = 0.f;
            #pragma unroll
            for (int i = 0; i < 8; i++) { sw += part[0][i]; sl += part[1][i]; }
            wm[bn] = sw * (1.f/1048576.f);
            Lm[bn] = fmaxf(sl * (1.f/1048576.f), 0.05f);
        }
        __syncthreads();
    }
    if (t == 0) {
        for (int bb = 0; bb < 4; bb++) {
            float num = 0.f, den = 1e-6f;
            #pragma unroll
            for (int n = 0; n < 5; n++) { num += Lm[bb*5+n]*wm[bb*5+n]; den += wm[bb*5+n]; }
            float target = num / den;
            #pragma unroll
            for (int n = 0; n < 5; n++) g_scale[bb*5+n] = target / Lm[bb*5+n];
        }
        g_cnt_q = 0;   // reset for graph replay
    }
}

// ---------------- K5: fused blur+pool downsample, 64x16 out tile -----------------
__global__ void __launch_bounds__(256) k_down(const float* __restrict__ inA,
                       const float* __restrict__ inB,
                       float* __restrict__ outA, float* __restrict__ outB,
                       int Hi, int Wi, int lvl0) {
    __shared__ float tile[36][132];
    int x0 = blockIdx.x * 64;
    int y0 = blockIdx.y * 16;
    int z = blockIdx.z;
    bool isA = z < NIMG;
    int img = isA ? z : z - NIMG;
    int Ho = Hi >> 1, Wo = Wi >> 1;
    const float* src = (isA ? inA : inB) + (size_t)img * Hi * Wi;
    float* dst = (isA ? outA : outB) + (size_t)img * Ho * Wo;
    bool doclip = lvl0 && isA;
    float sc = doclip ? g_scale[img] : 1.f;
    int t = threadIdx.x;
    for (int idx = t; idx < 36*132; idx += 256) {
        int r = idx / 132, c = idx - r*132;
        int gy = 2*y0 - 2 + r;
        int gx = 2*x0 - 2 + c;
        float v = 0.f;
        if (gy >= 0 && gy < Hi && gx >= 0 && gx < Wi) {
            v = src[(size_t)gy * Wi + gx];
            if (doclip) v = fminf(fmaxf(v * sc, 0.f), 1.f);
        }
        tile[r][c] = v;
    }
    __syncthreads();
    int tx = t & 63, ty = t >> 6;       // ty in 0..3, rows 4*ty .. 4*ty+3
    const float kk[6] = {1.f/32, 5.f/32, 10.f/32, 10.f/32, 5.f/32, 1.f/32};
    float rs[12];
    int c0 = 2*tx;
    #pragma unroll
    for (int rr = 0; rr < 12; rr++) {
        const float* rowp = &tile[8*ty + rr][c0];
        rs[rr] = kk[0]*rowp[0] + kk[1]*rowp[1] + kk[2]*rowp[2]
               + kk[3]*rowp[3] + kk[4]*rowp[4] + kk[5]*rowp[5];
    }
    #pragma unroll
    for (int j = 0; j < 4; j++) {
        float acc = kk[0]*rs[2*j] + kk[1]*rs[2*j+1] + kk[2]*rs[2*j+2]
                  + kk[3]*rs[2*j+3] + kk[4]*rs[2*j+4] + kk[5]*rs[2*j+5];
        dst[(size_t)(y0 + 4*ty + j) * Wo + (x0 + tx)] = acc;
    }
}

// ---------------- bilinear 2x upsample helper ------------------------------------
__device__ __forceinline__ float up1(const float* __restrict__ s, int Hs, int Ws,
                                     int y, int x) {
    int iy = (y - 1) >> 1, ix = (x - 1) >> 1;
    float fy = (y & 1) ? 0.25f : 0.75f;
    float fx = (x & 1) ? 0.25f : 0.75f;
    int y0 = max(iy, 0), y1 = min(iy + 1, Hs - 1);
    int x0 = max(ix, 0), x1 = min(ix + 1, Ws - 1);
    float a = s[(size_t)y0*Ws + x0], b = s[(size_t)y0*Ws + x1];
    float c = s[(size_t)y1*Ws + x0], d = s[(size_t)y1*Ws + x1];
    float top = a + fx*(b - a);
    float bot = c + fx*(d - c);
    return top + fy*(bot - top);
}

// ---------------- K6: 128-level blend with inline P4 (blend4 folded in) ----------
__device__ __forceinline__ float p4at(int b, int j, int i) {
    float s = 1e-6f, a = 0.f;
    #pragma unroll
    for (int n = 0; n < 5; n++) {
        size_t o = (size_t)(b*5+n)*4096 + j*64 + i;
        float gw = g_GW4[o];
        s += gw;
        a += g_GL4[o] * gw;
    }
    return __fdividef(a, s);
}

__global__ void k_blend128() {
    int idx = blockIdx.x*256 + threadIdx.x;
    if (idx >= 4*128*128) return;
    int b = idx >> 14;
    int rem = idx & 16383;
    int y = rem >> 7, x = rem & 127;
    float wv[5]; float qs = 1e-6f;
    #pragma unroll
    for (int n = 0; n < 5; n++) {
        wv[n] = g_GW3[(size_t)(b*5+n)*16384 + rem];
        qs += wv[n];
    }
    float inv = __fdividef(1.f, qs);
    int iy = (y - 1) >> 1, ix = (x - 1) >> 1;
    float fy = (y & 1) ? 0.25f : 0.75f;
    float fx = (x & 1) ? 0.25f : 0.75f;
    int y0 = max(iy, 0), y1 = min(iy + 1, 63);
    int x0 = max(ix, 0), x1 = min(ix + 1, 63);
    float a = p4at(b, y0, x0), bb = p4at(b, y0, x1);
    float c = p4at(b, y1, x0), d = p4at(b, y1, x1);
    float top = a + fx*(bb - a);
    float bot = c + fx*(d - c);
    float acc = top + fy*(bot - top);
    #pragma unroll
    for (int n = 0; n < 5; n++) {
        float lap = g_GL3[(size_t)(b*5+n)*16384 + rem]
                  - up1(g_GL4 + (size_t)(b*5+n)*4096, 64, 64, y, x);
        acc += lap * wv[n] * inv;
    }
    g_P3[idx] = acc;
}

// ---------------- K7: mid blend, 2 horizontal px per thread ----------------------
__global__ void k_blend2(const float* __restrict__ GL, const float* __restrict__ GLn,
                         const float* __restrict__ GW, const float* __restrict__ pin,
                         float* __restrict__ pout, int H, int W) {
    int idx = blockIdx.x*256 + threadIdx.x;
    int W2 = W >> 1;
    int total = 4*H*W2;
    if (idx >= total) return;
    int b = idx / (H*W2);
    int rem2 = idx - b*(H*W2);
    int y = rem2 / W2, i = rem2 - y*W2;     // output px pair (y, 2i) (y, 2i+1)
    int Hn = H>>1, Wn = W>>1;
    size_t rowoff = (size_t)y*W + 2*i;
    float2 wv[5]; float2 qs = make_float2(1e-6f, 1e-6f);
    #pragma unroll
    for (int n = 0; n < 5; n++) {
        float2 t = *reinterpret_cast<const float2*>(GW + (size_t)(b*5+n)*H*W + rowoff);
        wv[n] = t;
        qs.x += t.x; qs.y += t.y;
    }
    float2 inv = make_float2(__fdividef(1.f, qs.x), __fdividef(1.f, qs.y));
    int iy = (y - 1) >> 1;
    float fy = (y & 1) ? 0.25f : 0.75f;
    int ry0 = max(iy, 0), ry1 = min(iy + 1, Hn - 1);
    int c0 = max(i - 1, 0);
    int c1 = i;
    int c2 = min(i + 1, Wn - 1);
    float2 acc;
    {
        const float* r0 = pin + (size_t)b*Hn*Wn + (size_t)ry0*Wn;
        const float* r1 = pin + (size_t)b*Hn*Wn + (size_t)ry1*Wn;
        float a0=r0[c0], a1=r0[c1], a2=r0[c2];
        float b0=r1[c0], b1=r1[c1], b2=r1[c2];
        float hx0 = a0 + 0.75f*(a1-a0), hx1 = a1 + 0.25f*(a2-a1);
        float gx0 = b0 + 0.75f*(b1-b0), gx1 = b1 + 0.25f*(b2-b1);
        acc.x = hx0 + fy*(gx0-hx0);
        acc.y = hx1 + fy*(gx1-hx1);
    }
    #pragma unroll
    for (int n = 0; n < 5; n++) {
        float2 gl = *reinterpret_cast<const float2*>(GL + (size_t)(b*5+n)*H*W + rowoff);
        const float* r0 = GLn + (size_t)(b*5+n)*Hn*Wn + (size_t)ry0*Wn;
        const float* r1 = GLn + (size_t)(b*5+n)*Hn*Wn + (size_t)ry1*Wn;
        float a0=r0[c0], a1=r0[c1], a2=r0[c2];
        float b0=r1[c0], b1=r1[c1], b2=r1[c2];
        float hx0 = a0 + 0.75f*(a1-a0), hx1 = a1 + 0.25f*(a2-a1);
        float gx0 = b0 + 0.75f*(b1-b0), gx1 = b1 + 0.25f*(b2-b1);
        float u0 = hx0 + fy*(gx0-hx0);
        float u1 = hx1 + fy*(gx1-hx1);
        acc.x += (gl.x - u0) * wv[n].x * inv.x;
        acc.y += (gl.y - u1) * wv[n].y * inv.y;
    }
    *reinterpret_cast<float2*>(pout + (size_t)b*H*W + rowoff) = acc;
}

// ---------------- K8: final — smem-tiled upsample + lap0 + blend + collapse ------
__global__ void k_final(const float* __restrict__ L, const float* __restrict__ w,
                        float* __restrict__ out) {
    __shared__ float sm[6][6][68];   // planes 0..4 = GL1 n, 5 = P1
    int s  = blockIdx.x;   // col tile (128 out px)
    int tY = blockIdx.y;   // row tile (8 out rows)
    int b  = blockIdx.z;
    int t  = threadIdx.x;
    int cbase = 64*s - 1;
    int rbase = 4*tY - 1;
    for (int idx = t; idx < 6*6*68; idx += 256) {
        int pl = idx / (6*68);
        int rem = idx - pl*6*68;
        int rr = rem / 68, cc = rem - rr*68;
        int rs = min(max(rbase + rr, 0), 511);
        int cs = min(max(cbase + cc, 0), 511);
        float v;
        if (pl < 5) v = g_GL1[((size_t)(b*5+pl)*512 + rs)*512 + cs];
        else        v = g_P1 [((size_t)b*512 + rs)*512 + cs];
        sm[pl][rr][cc] = v;
    }
    __syncthreads();
    int mm = t & 31;
    int r  = t >> 5;
    int y  = 8*tY + r;
    float fy = (r & 1) ? 0.25f : 0.75f;
    int rr0 = ((r - 1) >> 1) + 1;
    int rr1 = rr0 + 1;
    int jc = 2*mm;
    int xo = 128*s + 4*mm;
    size_t po = (size_t)y*1024 + xo;

    float4 acc, u[5];
    {
        #pragma unroll
        for (int pl = 0; pl < 6; pl++) {
            float a0 = sm[pl][rr0][jc],   a1 = sm[pl][rr0][jc+1];
            float a2 = sm[pl][rr0][jc+2], a3 = sm[pl][rr0][jc+3];
            float c0 = sm[pl][rr1][jc],   c1 = sm[pl][rr1][jc+1];
            float c2 = sm[pl][rr1][jc+2], c3 = sm[pl][rr1][jc+3];
            float h0a = a0 + 0.75f*(a1-a0);
            float h1a = a1 + 0.25f*(a2-a1);
            float h2a = a1 + 0.75f*(a2-a1);
            float h3a = a2 + 0.25f*(a3-a2);
            float h0b = c0 + 0.75f*(c1-c0);
            float h1b = c1 + 0.25f*(c2-c1);
            float h2b = c1 + 0.75f*(c2-c1);
            float h3b = c2 + 0.25f*(c3-c2);
            float4 rv;
            rv.x = h0a + fy*(h0b-h0a);
            rv.y = h1a + fy*(h1b-h1a);
            rv.z = h2a + fy*(h2b-h2a);
            rv.w = h3a + fy*(h3b-h3a);
            if (pl < 5) u[pl] = rv; else acc = rv;
        }
    }
    float4 W5[5];
    float4 ws = make_float4(1e-6f, 1e-6f, 1e-6f, 1e-6f);
    #pragma unroll
    for (int n = 0; n < 5; n++) {
        float4 wn = *reinterpret_cast<const float4*>(w + (size_t)(b*5+n)*HW + po);
        W5[n] = wn;
        ws.x += wn.x; ws.y += wn.y; ws.z += wn.z; ws.w += wn.w;
    }
    float4 inv;
    inv.x = __fdividef(1.f, ws.x); inv.y = __fdividef(1.f, ws.y);
    inv.z = __fdividef(1.f, ws.z); inv.w = __fdividef(1.f, ws.w);
    #pragma unroll
    for (int n = 0; n < 5; n++) {
        int bn = b*5+n;
        float4 Ln = *reinterpret_cast<const float4*>(L + (size_t)bn*HW + po);
        float scv = g_scale[bn];
        acc.x += (fminf(fmaxf(Ln.x*scv, 0.f), 1.f) - u[n].x) * W5[n].x * inv.x;
        acc.y += (fminf(fmaxf(Ln.y*scv, 0.f), 1.f) - u[n].y) * W5[n].y * inv.y;
        acc.z += (fminf(fmaxf(Ln.z*scv, 0.f), 1.f) - u[n].z) * W5[n].z * inv.z;
        acc.w += (fminf(fmaxf(Ln.w*scv, 0.f), 1.f) - u[n].w) * W5[n].w * inv.w;
    }
    acc.x = fminf(fmaxf(acc.x, 0.f), 1.f);
    acc.y = fminf(fmaxf(acc.y, 0.f), 1.f);
    acc.z = fminf(fmaxf(acc.z, 0.f), 1.f);
    acc.w = fminf(fmaxf(acc.w, 0.f), 1.f);
    *reinterpret_cast<float4*>(out + (size_t)b*HW + po) = acc;
}

// ---------------- launcher -------------------------------------------------------
extern "C" void kernel_launch(void* const* d_in, const int* in_sizes, int n_in,
                              void* d_out, int out_size) {
    const float* L = (const float*)d_in[0];
    float* out = (float*)d_out;
    float* w = out + (size_t)4*HW;

    float *pGL1,*pGL2,*pGL3,*pGL4,*pGW1,*pGW2,*pGW3,*pGW4,*pP1,*pP2,*pP3;
    cudaGetSymbolAddress((void**)&pGL1, g_GL1);
    cudaGetSymbolAddress((void**)&pGL2, g_GL2);
    cudaGetSymbolAddress((void**)&pGL3, g_GL3);
    cudaGetSymbolAddress((void**)&pGL4, g_GL4);
    cudaGetSymbolAddress((void**)&pGW1, g_GW1);
    cudaGetSymbolAddress((void**)&pGW2, g_GW2);
    cudaGetSymbolAddress((void**)&pGW3, g_GW3);
    cudaGetSymbolAddress((void**)&pGW4, g_GW4);
    cudaGetSymbolAddress((void**)&pP1,  g_P1);
    cudaGetSymbolAddress((void**)&pP2,  g_P2);
    cudaGetSymbolAddress((void**)&pP3,  g_P3);

    // quality / weights / stats (voff + statscale folded in via last-block pattern)
    k_hvscan   <<<dim3(32,20), 256>>>(L);
    k_quality  <<<dim3(1024,4), 256>>>(L, w);

    // gaussian pyramids (L with inline scale+clip at level 0; L and w fused, z=40)
    k_down<<<dim3(8,32,40), 256>>>(L,    w,    pGL1, pGW1, 1024, 1024, 1);
    k_down<<<dim3(4,16,40), 256>>>(pGL1, pGW1, pGL2, pGW2,  512,  512, 0);
    k_down<<<dim3(2, 8,40), 256>>>(pGL2, pGW2, pGL3, pGW3,  256,  256, 0);
    k_down<<<dim3(1, 4,40), 256>>>(pGL3, pGW3, pGL4, pGW4,  128,  128, 0);

    // blend + collapse (laplacians inline; top blend folded into 128-level)
    k_blend128<<<(4*128*128+255)/256, 256>>>();
    k_blend2<<<(4*256*128+255)/256, 256>>>(pGL2, pGL3, pGW2, pP3, pP2, 256, 256);
    k_blend2<<<(4*512*256+255)/256, 256>>>(pGL1, pGL2, pGW1, pP2, pP1, 512, 512);
    k_final<<<dim3(8,128,4), 256>>>(L, w, out);
}

// round 16
// speedup vs baseline: 1.1208x; 1.1208x over previous
#include <cuda_runtime.h>

#define HW (1024*1024)
#define NIMG 20

// ---------------- static device scratch ----------------
__device__ float g_S1  [NIMG*HW];        // vertical strip-local prefix of hbox sums
__device__ float g_vp  [NIMG*32*1024];   // per-strip vertical offsets [img][strip][col]
__device__ float g_GL1 [NIMG*512*512];
__device__ float g_GL2 [NIMG*256*256];
__device__ float g_GL3 [NIMG*128*128];
__device__ float g_GL4 [NIMG*64*64];
__device__ float g_GW1 [NIMG*512*512];
__device__ float g_GW2 [NIMG*256*256];
__device__ float g_GW3 [NIMG*128*128];
__device__ float g_GW4 [NIMG*64*64];
__device__ float g_P1  [4*512*512];
__device__ float g_P2  [4*256*256];
__device__ float g_P3  [4*128*128];
__device__ float g_Lpart [NIMG*32];
__device__ float g_wpart [NIMG*1024];
__device__ float g_scale[NIMG];

// ---- K1: fused horizontal box + vertical strip prefix, 2 rows per iteration -----
__global__ void __launch_bounds__(256) k_hvscan(const float* __restrict__ L) {
    int strip = blockIdx.x;            // 0..31
    int img   = blockIdx.y;            // 0..19
    int t = threadIdx.x;
    int lane = t & 31, wid = t >> 5;
    __shared__ float P[2][1024];
    __shared__ float woff[2][8];
    __shared__ float lred[8];
    float v0 = 0.f, v1 = 0.f, v2 = 0.f, v3 = 0.f;   // vertical running sums (4 cols)
    float lacc = 0.f;
    size_t base = ((size_t)img * 1024 + strip * 32) * 1024;
    const float4* src = reinterpret_cast<const float4*>(L + base);
    float4* dst = reinterpret_cast<float4*>(g_S1 + base);

    for (int r = 0; r < 32; r += 2) {
        float4 vA = src[r * 256 + t];
        float4 vB = src[(r + 1) * 256 + t];
        lacc += (vA.x + vA.y) + (vA.z + vA.w);
        lacc += (vB.x + vB.y) + (vB.z + vB.w);
        float a0 = fmaxf(vA.x - 0.88f, 0.f), a1 = fmaxf(vA.y - 0.88f, 0.f);
        float a2 = fmaxf(vA.z - 0.88f, 0.f), a3 = fmaxf(vA.w - 0.88f, 0.f);
        float b0 = fmaxf(vB.x - 0.88f, 0.f), b1 = fmaxf(vB.y - 0.88f, 0.f);
        float b2 = fmaxf(vB.z - 0.88f, 0.f), b3 = fmaxf(vB.w - 0.88f, 0.f);
        float pA0 = a0, pA1 = pA0 + a1, pA2 = pA1 + a2, pA3 = pA2 + a3;
        float pB0 = b0, pB1 = pB0 + b1, pB2 = pB1 + b2, pB3 = pB2 + b3;
        float scA = pA3, scB = pB3;
        #pragma unroll
        for (int o = 1; o < 32; o <<= 1) {
            float nA = __shfl_up_sync(0xffffffffu, scA, o);
            float nB = __shfl_up_sync(0xffffffffu, scB, o);
            if (lane >= o) { scA += nA; scB += nB; }
        }
        if (lane == 31) { woff[0][wid] = scA; woff[1][wid] = scB; }
        __syncthreads();
        float bsA = scA - pA3, bsB = scB - pB3;
        #pragma unroll
        for (int i = 0; i < 8; i++) {
            if (i < wid) { bsA += woff[0][i]; bsB += woff[1][i]; }
        }
        P[0][4*t+0] = bsA + pA0;
        P[0][4*t+1] = bsA + pA1;
        P[0][4*t+2] = bsA + pA2;
        P[0][4*t+3] = bsA + pA3;
        P[1][4*t+0] = bsB + pB0;
        P[1][4*t+1] = bsB + pB1;
        P[1][4*t+2] = bsB + pB2;
        P[1][4*t+3] = bsB + pB3;
        __syncthreads();
        int xi = 4*t;
        int hi0 = min(xi + 30, 1023), lo0 = xi - 31;
        int hi1 = min(xi + 31, 1023), lo1 = xi - 30;
        int hi2 = min(xi + 32, 1023), lo2 = xi - 29;
        int hi3 = min(xi + 33, 1023), lo3 = xi - 28;
        {
            float h0 = P[0][hi0] - (lo0 >= 0 ? P[0][lo0] : 0.f);
            float h1 = P[0][hi1] - (lo1 >= 0 ? P[0][lo1] : 0.f);
            float h2 = P[0][hi2] - (lo2 >= 0 ? P[0][lo2] : 0.f);
            float h3 = P[0][hi3] - (lo3 >= 0 ? P[0][lo3] : 0.f);
            v0 += h0; v1 += h1; v2 += h2; v3 += h3;
            float4 o4; o4.x = v0; o4.y = v1; o4.z = v2; o4.w = v3;
            dst[r * 256 + t] = o4;
        }
        {
            float h0 = P[1][hi0] - (lo0 >= 0 ? P[1][lo0] : 0.f);
            float h1 = P[1][hi1] - (lo1 >= 0 ? P[1][lo1] : 0.f);
            float h2 = P[1][hi2] - (lo2 >= 0 ? P[1][lo2] : 0.f);
            float h3 = P[1][hi3] - (lo3 >= 0 ? P[1][lo3] : 0.f);
            v0 += h0; v1 += h1; v2 += h2; v3 += h3;
            float4 o4; o4.x = v0; o4.y = v1; o4.z = v2; o4.w = v3;
            dst[(r + 1) * 256 + t] = o4;
        }
    }
    float4* vpd = reinterpret_cast<float4*>(g_vp + ((size_t)img*32 + strip)*1024);
    float4 tot; tot.x = v0; tot.y = v1; tot.z = v2; tot.w = v3;
    vpd[t] = tot;
    #pragma unroll
    for (int o = 16; o; o >>= 1) lacc += __shfl_down_sync(0xffffffffu, lacc, o);
    if (lane == 0) lred[wid] = lacc;
    __syncthreads();
    if (t == 0) {
        float s = 0.f;
        #pragma unroll
        for (int i = 0; i < 8; i++) s += lred[i];
        g_Lpart[img*32 + strip] = s;
    }
}

// ---------------- K2b: exclusive prefix over 32 strip totals (float4 cols, MLP8) -
__global__ void k_voff() {
    int idx = blockIdx.x*256 + threadIdx.x;   // NIMG*256 float4 columns
    if (idx >= NIMG*256) return;
    int img = idx >> 8, col4 = idx & 255;
    float4* p = reinterpret_cast<float4*>(g_vp + (size_t)img*32*1024) + col4;
    float4 run = make_float4(0.f, 0.f, 0.f, 0.f);
    #pragma unroll
    for (int c = 0; c < 4; c++) {
        float4 v[8];
        #pragma unroll
        for (int i = 0; i < 8; i++) v[i] = p[(c*8+i)*256];
        #pragma unroll
        for (int i = 0; i < 8; i++) {
            float4 tv = v[i];
            p[(c*8+i)*256] = run;
            run.x += tv.x; run.y += tv.y; run.z += tv.z; run.w += tv.w;
        }
    }
}

// ---------------- K2c: quality + w, float4 per thread ----------------------------
__device__ __forceinline__ float quality1(float Lv, float V) {
    const float cb = -15.f / 3721.f;
    float u = 2.f*Lv - 1.f;
    float t1 = 1.f - u*u;
    float baseq = t1*t1;
    float sat  = __fdividef(1.f, 1.f + __expf( 15.f*(Lv - 0.88f)));
    float dark = __fdividef(1.f, 1.f + __expf(-25.f*(Lv - 0.04f)));
    float bloom = __expf(cb * V);
    return fmaxf(baseq*sat*dark*bloom, 0.02f);
}

__global__ void __launch_bounds__(256) k_quality(const float* __restrict__ L,
                                                 float* __restrict__ wout) {
    int t = threadIdx.x;          // float4 index: 256 * 4 = 1024 px per row
    int y = blockIdx.x;
    int b = blockIdx.y;
    int lane = t & 31, wid = t >> 5;
    int ya = min(y + 30, 1023);
    int yb = y - 31;
    float4 q[5];
    float4 qs = make_float4(1e-6f, 1e-6f, 1e-6f, 1e-6f);
    #pragma unroll
    for (int n = 0; n < 5; n++) {
        int img = b*5 + n;
        const float* Sbase  = g_S1 + (size_t)img*HW;
        const float* vpbase = g_vp + (size_t)img*32*1024;
        float4 Sa = reinterpret_cast<const float4*>(Sbase + (size_t)ya*1024)[t];
        float4 va = reinterpret_cast<const float4*>(vpbase + (ya>>5)*1024)[t];
        float4 V;
        V.x = Sa.x + va.x; V.y = Sa.y + va.y; V.z = Sa.z + va.z; V.w = Sa.w + va.w;
        if (yb >= 0) {
            float4 Sb = reinterpret_cast<const float4*>(Sbase + (size_t)yb*1024)[t];
            float4 vb = reinterpret_cast<const float4*>(vpbase + (yb>>5)*1024)[t];
            V.x -= Sb.x + vb.x; V.y -= Sb.y + vb.y; V.z -= Sb.z + vb.z; V.w -= Sb.w + vb.w;
        }
        float4 Lv = reinterpret_cast<const float4*>(L + (size_t)img*HW + (size_t)y*1024)[t];
        float4 qn;
        qn.x = quality1(Lv.x, V.x);
        qn.y = quality1(Lv.y, V.y);
        qn.z = quality1(Lv.z, V.z);
        qn.w = quality1(Lv.w, V.w);
        q[n] = qn;
        qs.x += qn.x; qs.y += qn.y; qs.z += qn.z; qs.w += qn.w;
    }
    float4 inv;
    inv.x = __fdividef(1.f, qs.x); inv.y = __fdividef(1.f, qs.y);
    inv.z = __fdividef(1.f, qs.z); inv.w = __fdividef(1.f, qs.w);
    __shared__ float sred[5][8];
    #pragma unroll
    for (int n = 0; n < 5; n++) {
        float4 wv;
        wv.x = q[n].x*inv.x; wv.y = q[n].y*inv.y;
        wv.z = q[n].z*inv.z; wv.w = q[n].w*inv.w;
        reinterpret_cast<float4*>(wout + (size_t)(b*5+n)*HW + (size_t)y*1024)[t] = wv;
        float s = (wv.x + wv.y) + (wv.z + wv.w);
        #pragma unroll
        for (int o = 16; o; o >>= 1) s += __shfl_down_sync(0xffffffffu, s, o);
        if (lane == 0) sred[n][wid] = s;
    }
    __syncthreads();
    if (t < 5) {
        float s = 0.f;
        #pragma unroll
        for (int i = 0; i < 8; i++) s += sred[t][i];
        g_wpart[(size_t)(b*5+t)*1024 + y] = s;
    }
}

// ---------------- K3: means + exposure scales (shuffle reduction, 1 sync) --------
__global__ void __launch_bounds__(256) k_statscale() {
    int b = blockIdx.x;     // 4 blocks
    int t = threadIdx.x;    // 256
    int lane = t & 31, wid = t >> 5;
    float acc[10];
    #pragma unroll
    for (int n = 0; n < 5; n++) {
        int bn = b*5 + n;
        float a = 0.f;
        for (int i = t; i < 1024; i += 256) a += g_wpart[bn*1024 + i];
        acc[n] = a;
        acc[5+n] = (t < 32) ? g_Lpart[bn*32 + t] : 0.f;
    }
    #pragma unroll
    for (int k = 0; k < 10; k++) {
        #pragma unroll
        for (int o = 16; o; o >>= 1)
            acc[k] += __shfl_down_sync(0xffffffffu, acc[k], o);
    }
    __shared__ float part[10][8];
    if (lane == 0) {
        #pragma unroll
        for (int k = 0; k < 10; k++) part[k][wid] = acc[k];
    }
    __syncthreads();
    if (t == 0) {
        float num = 0.f, den = 1e-6f;
        float Lm[5], wm[5];
        #pragma unroll
        for (int n = 0; n < 5; n++) {
            float sw = 0.f, sl = 0.f;
            #pragma unroll
            for (int i = 0; i < 8; i++) { sw += part[n][i]; sl += part[5+n][i]; }
            wm[n] = sw * (1.f/1048576.f);
            Lm[n] = fmaxf(sl * (1.f/1048576.f), 0.05f);
            num += Lm[n]*wm[n]; den += wm[n];
        }
        float target = num / den;
        #pragma unroll
        for (int n = 0; n < 5; n++) g_scale[b*5+n] = target / Lm[n];
    }
}

// ---------------- K5: fused blur+pool downsample, 64x16 out tile -----------------
__global__ void __launch_bounds__(256) k_down(const float* __restrict__ inA,
                       const float* __restrict__ inB,
                       float* __restrict__ outA, float* __restrict__ outB,
                       int Hi, int Wi, int lvl0) {
    __shared__ float tile[36][132];
    int x0 = blockIdx.x * 64;
    int y0 = blockIdx.y * 16;
    int z = blockIdx.z;
    bool isA = z < NIMG;
    int img = isA ? z : z - NIMG;
    int Ho = Hi >> 1, Wo = Wi >> 1;
    const float* src = (isA ? inA : inB) + (size_t)img * Hi * Wi;
    float* dst = (isA ? outA : outB) + (size_t)img * Ho * Wo;
    bool doclip = lvl0 && isA;
    float sc = doclip ? g_scale[img] : 1.f;
    int t = threadIdx.x;
    for (int idx = t; idx < 36*132; idx += 256) {
        int r = idx / 132, c = idx - r*132;
        int gy = 2*y0 - 2 + r;
        int gx = 2*x0 - 2 + c;
        float v = 0.f;
        if (gy >= 0 && gy < Hi && gx >= 0 && gx < Wi) {
            v = src[(size_t)gy * Wi + gx];
            if (doclip) v = fminf(fmaxf(v * sc, 0.f), 1.f);
        }
        tile[r][c] = v;
    }
    __syncthreads();
    int tx = t & 63, ty = t >> 6;       // ty in 0..3, rows 4*ty .. 4*ty+3
    const float kk[6] = {1.f/32, 5.f/32, 10.f/32, 10.f/32, 5.f/32, 1.f/32};
    float rs[12];
    int c0 = 2*tx;
    #pragma unroll
    for (int rr = 0; rr < 12; rr++) {
        const float* rowp = &tile[8*ty + rr][c0];
        rs[rr] = kk[0]*rowp[0] + kk[1]*rowp[1] + kk[2]*rowp[2]
               + kk[3]*rowp[3] + kk[4]*rowp[4] + kk[5]*rowp[5];
    }
    #pragma unroll
    for (int j = 0; j < 4; j++) {
        float acc = kk[0]*rs[2*j] + kk[1]*rs[2*j+1] + kk[2]*rs[2*j+2]
                  + kk[3]*rs[2*j+3] + kk[4]*rs[2*j+4] + kk[5]*rs[2*j+5];
        dst[(size_t)(y0 + 4*ty + j) * Wo + (x0 + tx)] = acc;
    }
}

// ---------------- bilinear 2x upsample helper ------------------------------------
__device__ __forceinline__ float up1(const float* __restrict__ s, int Hs, int Ws,
                                     int y, int x) {
    int iy = (y - 1) >> 1, ix = (x - 1) >> 1;
    float fy = (y & 1) ? 0.25f : 0.75f;
    float fx = (x & 1) ? 0.25f : 0.75f;
    int y0 = max(iy, 0), y1 = min(iy + 1, Hs - 1);
    int x0 = max(ix, 0), x1 = min(ix + 1, Ws - 1);
    float a = s[(size_t)y0*Ws + x0], b = s[(size_t)y0*Ws + x1];
    float c = s[(size_t)y1*Ws + x0], d = s[(size_t)y1*Ws + x1];
    float top = a + fx*(b - a);
    float bot = c + fx*(d - c);
    return top + fy*(bot - top);
}

// ---------------- K6: 128-level blend with inline P4 (blend4 folded in) ----------
__device__ __forceinline__ float p4at(int b, int j, int i) {
    float s = 1e-6f, a = 0.f;
    #pragma unroll
    for (int n = 0; n < 5; n++) {
        size_t o = (size_t)(b*5+n)*4096 + j*64 + i;
        float gw = g_GW4[o];
        s += gw;
        a += g_GL4[o] * gw;
    }
    return __fdividef(a, s);
}

__global__ void k_blend128() {
    int idx = blockIdx.x*256 + threadIdx.x;
    if (idx >= 4*128*128) return;
    int b = idx >> 14;
    int rem = idx & 16383;
    int y = rem >> 7, x = rem & 127;
    float wv[5]; float qs = 1e-6f;
    #pragma unroll
    for (int n = 0; n < 5; n++) {
        wv[n] = g_GW3[(size_t)(b*5+n)*16384 + rem];
        qs += wv[n];
    }
    float inv = __fdividef(1.f, qs);
    int iy = (y - 1) >> 1, ix = (x - 1) >> 1;
    float fy = (y & 1) ? 0.25f : 0.75f;
    float fx = (x & 1) ? 0.25f : 0.75f;
    int y0 = max(iy, 0), y1 = min(iy + 1, 63);
    int x0 = max(ix, 0), x1 = min(ix + 1, 63);
    float a = p4at(b, y0, x0), bb = p4at(b, y0, x1);
    float c = p4at(b, y1, x0), d = p4at(b, y1, x1);
    float top = a + fx*(bb - a);
    float bot = c + fx*(d - c);
    float acc = top + fy*(bot - top);
    #pragma unroll
    for (int n = 0; n < 5; n++) {
        float lap = g_GL3[(size_t)(b*5+n)*16384 + rem]
                  - up1(g_GL4 + (size_t)(b*5+n)*4096, 64, 64, y, x);
        acc += lap * wv[n] * inv;
    }
    g_P3[idx] = acc;
}

// ---------------- K7: mid blend, 4 horizontal px per thread (float4) -------------
__global__ void k_blend4px(const float* __restrict__ GL, const float* __restrict__ GLn,
                           const float* __restrict__ GW, const float* __restrict__ pin,
                           float* __restrict__ pout, int H, int W) {
    int idx = blockIdx.x*256 + threadIdx.x;
    int W4 = W >> 2;
    int total = 4*H*W4;
    if (idx >= total) return;
    int b = idx / (H*W4);
    int rem4 = idx - b*(H*W4);
    int y = rem4 / W4, i = rem4 - y*W4;     // output px (y, 4i..4i+3)
    int Hn = H>>1, Wn = W>>1;
    size_t rowoff = (size_t)y*W + 4*i;
    float4 wv[5]; float4 qs = make_float4(1e-6f, 1e-6f, 1e-6f, 1e-6f);
    #pragma unroll
    for (int n = 0; n < 5; n++) {
        float4 t4 = *reinterpret_cast<const float4*>(GW + (size_t)(b*5+n)*H*W + rowoff);
        wv[n] = t4;
        qs.x += t4.x; qs.y += t4.y; qs.z += t4.z; qs.w += t4.w;
    }
    float4 inv;
    inv.x = __fdividef(1.f, qs.x); inv.y = __fdividef(1.f, qs.y);
    inv.z = __fdividef(1.f, qs.z); inv.w = __fdividef(1.f, qs.w);
    int iy = (y - 1) >> 1;
    float fy = (y & 1) ? 0.25f : 0.75f;
    int ry0 = max(iy, 0), ry1 = min(iy + 1, Hn - 1);
    int c0 = max(2*i - 1, 0);
    int c1 = 2*i;
    int c2 = min(2*i + 1, Wn - 1);
    int c3 = min(2*i + 2, Wn - 1);
    float4 acc;
    {
        const float* r0 = pin + (size_t)b*Hn*Wn + (size_t)ry0*Wn;
        const float* r1 = pin + (size_t)b*Hn*Wn + (size_t)ry1*Wn;
        float a0=r0[c0], a1=r0[c1], a2=r0[c2], a3=r0[c3];
        float b0=r1[c0], b1=r1[c1], b2=r1[c2], b3=r1[c3];
        float h0a = a0 + 0.75f*(a1-a0);
        float h1a = a1 + 0.25f*(a2-a1);
        float h2a = a1 + 0.75f*(a2-a1);
        float h3a = a2 + 0.25f*(a3-a2);
        float h0b = b0 + 0.75f*(b1-b0);
        float h1b = b1 + 0.25f*(b2-b1);
        float h2b = b1 + 0.75f*(b2-b1);
        float h3b = b2 + 0.25f*(b3-b2);
        acc.x = h0a + fy*(h0b-h0a);
        acc.y = h1a + fy*(h1b-h1a);
        acc.z = h2a + fy*(h2b-h2a);
        acc.w = h3a + fy*(h3b-h3a);
    }
    #pragma unroll
    for (int n = 0; n < 5; n++) {
        float4 gl = *reinterpret_cast<const float4*>(GL + (size_t)(b*5+n)*H*W + rowoff);
        const float* r0 = GLn + (size_t)(b*5+n)*Hn*Wn + (size_t)ry0*Wn;
        const float* r1 = GLn + (size_t)(b*5+n)*Hn*Wn + (size_t)ry1*Wn;
        float a0=r0[c0], a1=r0[c1], a2=r0[c2], a3=r0[c3];
        float b0=r1[c0], b1=r1[c1], b2=r1[c2], b3=r1[c3];
        float h0a = a0 + 0.75f*(a1-a0);
        float h1a = a1 + 0.25f*(a2-a1);
        float h2a = a1 + 0.75f*(a2-a1);
        float h3a = a2 + 0.25f*(a3-a2);
        float h0b = b0 + 0.75f*(b1-b0);
        float h1b = b1 + 0.25f*(b2-b1);
        float h2b = b1 + 0.75f*(b2-b1);
        float h3b = b2 + 0.25f*(b3-b2);
        float u0 = h0a + fy*(h0b-h0a);
        float u1 = h1a + fy*(h1b-h1a);
        float u2 = h2a + fy*(h2b-h2a);
        float u3 = h3a + fy*(h3b-h3a);
        acc.x += (gl.x - u0) * wv[n].x * inv.x;
        acc.y += (gl.y - u1) * wv[n].y * inv.y;
        acc.z += (gl.z - u2) * wv[n].z * inv.z;
        acc.w += (gl.w - u3) * wv[n].w * inv.w;
    }
    *reinterpret_cast<float4*>(pout + (size_t)b*H*W + rowoff) = acc;
}

// ---------------- K8: final — smem-tiled upsample + lap0 + blend + collapse ------
__global__ void k_final(const float* __restrict__ L, const float* __restrict__ w,
                        float* __restrict__ out) {
    __shared__ float sm[6][6][68];   // planes 0..4 = GL1 n, 5 = P1
    int s  = blockIdx.x;   // col tile (128 out px)
    int tY = blockIdx.y;   // row tile (8 out rows)
    int b  = blockIdx.z;
    int t  = threadIdx.x;
    int cbase = 64*s - 1;
    int rbase = 4*tY - 1;
    for (int idx = t; idx < 6*6*68; idx += 256) {
        int pl = idx / (6*68);
        int rem = idx - pl*6*68;
        int rr = rem / 68, cc = rem - rr*68;
        int rs = min(max(rbase + rr, 0), 511);
        int cs = min(max(cbase + cc, 0), 511);
        float v;
        if (pl < 5) v = g_GL1[((size_t)(b*5+pl)*512 + rs)*512 + cs];
        else        v = g_P1 [((size_t)b*512 + rs)*512 + cs];
        sm[pl][rr][cc] = v;
    }
    __syncthreads();
    int mm = t & 31;
    int r  = t >> 5;
    int y  = 8*tY + r;
    float fy = (r & 1) ? 0.25f : 0.75f;
    int rr0 = ((r - 1) >> 1) + 1;
    int rr1 = rr0 + 1;
    int jc = 2*mm;
    int xo = 128*s + 4*mm;
    size_t po = (size_t)y*1024 + xo;

    float4 acc, u[5];
    {
        #pragma unroll
        for (int pl = 0; pl < 6; pl++) {
            float a0 = sm[pl][rr0][jc],   a1 = sm[pl][rr0][jc+1];
            float a2 = sm[pl][rr0][jc+2], a3 = sm[pl][rr0][jc+3];
            float c0 = sm[pl][rr1][jc],   c1 = sm[pl][rr1][jc+1];
            float c2 = sm[pl][rr1][jc+2], c3 = sm[pl][rr1][jc+3];
            float h0a = a0 + 0.75f*(a1-a0);
            float h1a = a1 + 0.25f*(a2-a1);
            float h2a = a1 + 0.75f*(a2-a1);
            float h3a = a2 + 0.25f*(a3-a2);
            float h0b = c0 + 0.75f*(c1-c0);
            float h1b = c1 + 0.25f*(c2-c1);
            float h2b = c1 + 0.75f*(c2-c1);
            float h3b = c2 + 0.25f*(c3-c2);
            float4 rv;
            rv.x = h0a + fy*(h0b-h0a);
            rv.y = h1a + fy*(h1b-h1a);
            rv.z = h2a + fy*(h2b-h2a);
            rv.w = h3a + fy*(h3b-h3a);
            if (pl < 5) u[pl] = rv; else acc = rv;
        }
    }
    float4 W5[5];
    float4 ws = make_float4(1e-6f, 1e-6f, 1e-6f, 1e-6f);
    #pragma unroll
    for (int n = 0; n < 5; n++) {
        float4 wn = *reinterpret_cast<const float4*>(w + (size_t)(b*5+n)*HW + po);
        W5[n] = wn;
        ws.x += wn.x; ws.y += wn.y; ws.z += wn.z; ws.w += wn.w;
    }
    float4 inv;
    inv.x = __fdividef(1.f, ws.x); inv.y = __fdividef(1.f, ws.y);
    inv.z = __fdividef(1.f, ws.z); inv.w = __fdividef(1.f, ws.w);
    #pragma unroll
    for (int n = 0; n < 5; n++) {
        int bn = b*5+n;
        float4 Ln = *reinterpret_cast<const float4*>(L + (size_t)bn*HW + po);
        float scv = g_scale[bn];
        acc.x += (fminf(fmaxf(Ln.x*scv, 0.f), 1.f) - u[n].x) * W5[n].x * inv.x;
        acc.y += (fminf(fmaxf(Ln.y*scv, 0.f), 1.f) - u[n].y) * W5[n].y * inv.y;
        acc.z += (fminf(fmaxf(Ln.z*scv, 0.f), 1.f) - u[n].z) * W5[n].z * inv.z;
        acc.w += (fminf(fmaxf(Ln.w*scv, 0.f), 1.f) - u[n].w) * W5[n].w * inv.w;
    }
    acc.x = fminf(fmaxf(acc.x, 0.f), 1.f);
    acc.y = fminf(fmaxf(acc.y, 0.f), 1.f);
    acc.z = fminf(fmaxf(acc.z, 0.f), 1.f);
    acc.w = fminf(fmaxf(acc.w, 0.f), 1.f);
    *reinterpret_cast<float4*>(out + (size_t)b*HW + po) = acc;
}

// ---------------- launcher -------------------------------------------------------
extern "C" void kernel_launch(void* const* d_in, const int* in_sizes, int n_in,
                              void* d_out, int out_size) {
    const float* L = (const float*)d_in[0];
    float* out = (float*)d_out;
    float* w = out + (size_t)4*HW;

    float *pGL1,*pGL2,*pGL3,*pGL4,*pGW1,*pGW2,*pGW3,*pGW4,*pP1,*pP2,*pP3;
    cudaGetSymbolAddress((void**)&pGL1, g_GL1);
    cudaGetSymbolAddress((void**)&pGL2, g_GL2);
    cudaGetSymbolAddress((void**)&pGL3, g_GL3);
    cudaGetSymbolAddress((void**)&pGL4, g_GL4);
    cudaGetSymbolAddress((void**)&pGW1, g_GW1);
    cudaGetSymbolAddress((void**)&pGW2, g_GW2);
    cudaGetSymbolAddress((void**)&pGW3, g_GW3);
    cudaGetSymbolAddress((void**)&pGW4, g_GW4);
    cudaGetSymbolAddress((void**)&pP1,  g_P1);
    cudaGetSymbolAddress((void**)&pP2,  g_P2);
    cudaGetSymbolAddress((void**)&pP3,  g_P3);

    // quality / weights / stats
    k_hvscan   <<<dim3(32,20), 256>>>(L);
    k_voff     <<<20, 256>>>();
    k_quality  <<<dim3(1024,4), 256>>>(L, w);
    k_statscale<<<4, 256>>>();

    // gaussian pyramids (L with inline scale+clip at level 0; L and w fused, z=40)
    k_down<<<dim3(8,32,40), 256>>>(L,    w,    pGL1, pGW1, 1024, 1024, 1);
    k_down<<<dim3(4,16,40), 256>>>(pGL1, pGW1, pGL2, pGW2,  512,  512, 0);
    k_down<<<dim3(2, 8,40), 256>>>(pGL2, pGW2, pGL3, pGW3,  256,  256, 0);
    k_down<<<dim3(1, 4,40), 256>>>(pGL3, pGW3, pGL4, pGW4,  128,  128, 0);

    // blend + collapse (laplacians inline; top blend folded into 128-level)
    k_blend128<<<(4*128*128+255)/256, 256>>>();
    k_blend4px<<<(4*256*64 +255)/256, 256>>>(pGL2, pGL3, pGW2, pP3, pP2, 256, 256);
    k_blend4px<<<(4*512*128+255)/256, 256>>>(pGL1, pGL2, pGW1, pP2, pP1, 512, 512);
    k_final<<<dim3(8,128,4), 256>>>(L, w, out);
}